// round 3
// baseline (speedup 1.0000x reference)
#include <cuda_runtime.h>
#include <cuda_bf16.h>
#include <math.h>

// ----------------------------------------------------------------------------
// CapsNet forward, fp32 baseline.
// Shapes: B=256, conv1: [B,256,20,20], prim: [B,256,6,6] -> u [B,1152,8]
// u_hat stored as [B][10][1152][16] for contiguous routing reductions.
// Output layout (concatenated, float32):
//   [0, 200704)        x
//   [200704, 241664)   v (output) [B,10,16,1]
//   [241664, 442368)   reconstruction [B,1,28,28]
//   [442368, 444928)   masked one-hot [B,10]
// ----------------------------------------------------------------------------

#define B_SZ 256
#define NUM_ROUTES 1152
#define NUM_CAPS 10
#define OUT_CH 16

__device__ float g_y[26214400];      // [256][256][400] conv1 out (relu)
__device__ float g_u[2359296];       // [256][9216] primary caps (squashed in-place)
__device__ float g_uhat[47185920];   // [256][10][1152][16]
__device__ float g_bij[11520];       // [1152][10]
__device__ float g_cij[11520];       // [1152][10]
__device__ float g_v[40960];         // [256][10][16]
__device__ int   g_idx[256];
__device__ float g_h1[131072];       // [256][512]
__device__ float g_h2[262144];       // [256][1024]

// ---------------------------------------------------------------- conv1
// grid (8 ocTiles, 256 batch), 256 threads. Register tile 8 oc x 2 pos.
__global__ __launch_bounds__(256) void conv1_kernel(
    const float* __restrict__ x, const float* __restrict__ w,
    const float* __restrict__ bias)
{
    int oct = blockIdx.x;     // 0..7, 32 ocs each
    int b   = blockIdx.y;
    int tid = threadIdx.x;

    __shared__ float simg[784];        // 28x28
    __shared__ float sw[32 * 81];      // [oc_local][k]

    for (int e = tid; e < 784; e += 256)  simg[e] = x[b * 784 + e];
    for (int e = tid; e < 2592; e += 256) sw[e]   = w[oct * 2592 + e];
    __syncthreads();

    int posA = tid;                 // always < 400
    int posB = tid + 256;
    bool hasB = (posB < 400);
    int oyA = posA / 20, oxA = posA % 20;
    int oyB = posB / 20, oxB = posB % 20;
    if (!hasB) { oyB = 0; oxB = 0; }

    for (int ocg = 0; ocg < 4; ocg++) {
        float accA[8], accB[8];
        #pragma unroll
        for (int j = 0; j < 8; j++) { accA[j] = 0.f; accB[j] = 0.f; }

        for (int ky = 0; ky < 9; ky++) {
            #pragma unroll
            for (int kx = 0; kx < 9; kx++) {
                float iA = simg[(oyA + ky) * 28 + oxA + kx];
                float iB = simg[(oyB + ky) * 28 + oxB + kx];
                const float* wp = sw + (ocg * 8) * 81 + ky * 9 + kx;
                #pragma unroll
                for (int j = 0; j < 8; j++) {
                    float wv = wp[j * 81];
                    accA[j] = fmaf(wv, iA, accA[j]);
                    accB[j] = fmaf(wv, iB, accB[j]);
                }
            }
        }
        #pragma unroll
        for (int j = 0; j < 8; j++) {
            int oc = oct * 32 + ocg * 8 + j;
            float bb = bias[oc];
            float* yp = g_y + ((size_t)b * 256 + oc) * 400;
            yp[posA] = fmaxf(accA[j] + bb, 0.f);
            if (hasB) yp[posB] = fmaxf(accB[j] + bb, 0.f);
        }
    }
}

// ---------------------------------------------------------------- primary conv
// grid (2 oc-halves, 256 batch), 192 threads = 32 ocg x 6 oy.
// Each thread: 4 ocs (ocg, ocg+32, ocg+64, ocg+96 within half) x 6 ox, fixed oy.
// Accumulators persist across the full ic loop.
__global__ __launch_bounds__(192) void prim_conv_kernel(
    const float* __restrict__ w, const float* __restrict__ pb)
{
    int half = blockIdx.x;
    int b    = blockIdx.y;
    int tid  = threadIdx.x;
    int ocg  = tid & 31;
    int oy   = tid >> 5;          // 0..5

    __shared__ float simg[400];               // 20x20 of current ic
    __shared__ float swk[81 * 129];           // [k][oc], stride 129 (conflict-free)

    float acc[4][6];
    #pragma unroll
    for (int j = 0; j < 4; j++)
        #pragma unroll
        for (int ox = 0; ox < 6; ox++) acc[j][ox] = 0.f;

    const float* ybase = g_y + (size_t)b * 256 * 400;

    for (int ic = 0; ic < 256; ic++) {
        for (int e = tid; e < 400; e += 192) simg[e] = ybase[ic * 400 + e];
        const float* wbase = w + ((size_t)(half * 128) * 256 + ic) * 81;
        for (int e = tid; e < 128 * 81; e += 192) {
            int o = e / 81;
            int k = e - o * 81;
            swk[k * 129 + o] = wbase[(size_t)o * (256 * 81) + k];
        }
        __syncthreads();

        for (int ky = 0; ky < 9; ky++) {
            const float* row = simg + (2 * oy + ky) * 20;
            #pragma unroll
            for (int kx = 0; kx < 9; kx++) {
                const float* wp = swk + (ky * 9 + kx) * 129 + ocg;
                float w0 = wp[0], w1 = wp[32], w2 = wp[64], w3 = wp[96];
                #pragma unroll
                for (int ox = 0; ox < 6; ox++) {
                    float iv = row[2 * ox + kx];
                    acc[0][ox] = fmaf(w0, iv, acc[0][ox]);
                    acc[1][ox] = fmaf(w1, iv, acc[1][ox]);
                    acc[2][ox] = fmaf(w2, iv, acc[2][ox]);
                    acc[3][ox] = fmaf(w3, iv, acc[3][ox]);
                }
            }
        }
        __syncthreads();
    }

    #pragma unroll
    for (int j = 0; j < 4; j++) {
        int c = half * 128 + ocg + 32 * j;
        float bb = pb[c];
        #pragma unroll
        for (int ox = 0; ox < 6; ox++)
            g_u[(size_t)b * 9216 + c * 36 + oy * 6 + ox] = acc[j][ox] + bb;
    }
}

// ---------------------------------------------------------------- squash (groups of 8)
__global__ void squash_kernel()
{
    int idx = blockIdx.x * blockDim.x + threadIdx.x;   // 294912 groups
    if (idx >= 294912) return;
    float* p = g_u + (size_t)idx * 8;
    float4 a = *(float4*)p;
    float4 c = *(float4*)(p + 4);
    float sn = a.x*a.x + a.y*a.y + a.z*a.z + a.w*a.w
             + c.x*c.x + c.y*c.y + c.z*c.z + c.w*c.w;
    float f = sn / ((1.f + sn) * sqrtf(sn));
    a.x*=f; a.y*=f; a.z*=f; a.w*=f; c.x*=f; c.y*=f; c.z*=f; c.w*=f;
    *(float4*)p = a;
    *(float4*)(p + 4) = c;
}

// ---------------------------------------------------------------- u_hat
// grid 1152 (route r), 160 threads = (c=tid/16, o=tid%16). W held in registers.
__global__ __launch_bounds__(160) void uhat_kernel(const float* __restrict__ W)
{
    int r   = blockIdx.x;
    int tid = threadIdx.x;
    int c = tid >> 4, o = tid & 15;

    const float* wp = W + (((size_t)r * 10 + c) * 16 + o) * 8;
    float4 wa = *(const float4*)wp;
    float4 wb = *(const float4*)(wp + 4);

    __shared__ float su[32][8];

    for (int b0 = 0; b0 < 256; b0 += 32) {
        for (int e = tid; e < 256; e += 160) {
            int j = e >> 3, i = e & 7;
            su[j][i] = g_u[(size_t)(b0 + j) * 9216 + r * 8 + i];
        }
        __syncthreads();
        #pragma unroll 4
        for (int j = 0; j < 32; j++) {
            const float* uu = su[j];
            float s = wa.x*uu[0] + wa.y*uu[1] + wa.z*uu[2] + wa.w*uu[3]
                    + wb.x*uu[4] + wb.y*uu[5] + wb.z*uu[6] + wb.w*uu[7];
            g_uhat[(((size_t)(b0 + j) * 10 + c) * 1152 + r) * 16 + o] = s;
        }
        __syncthreads();
    }
}

// ---------------------------------------------------------------- routing
__global__ void zero_b_kernel()
{
    int i = blockIdx.x * blockDim.x + threadIdx.x;
    if (i < 11520) g_bij[i] = 0.f;
}

// softmax over routes (axis 0) per class. grid 10, 256 threads.
__global__ void softmax_kernel()
{
    int c   = blockIdx.x;
    int tid = threadIdx.x;
    int lane = tid & 31, warp = tid >> 5;
    __shared__ float sred[8];
    __shared__ float s_max, s_sum;

    float m = -1e30f;
    for (int r = tid; r < 1152; r += 256) m = fmaxf(m, g_bij[r * 10 + c]);
    for (int off = 16; off >= 1; off >>= 1) m = fmaxf(m, __shfl_xor_sync(~0u, m, off));
    if (lane == 0) sred[warp] = m;
    __syncthreads();
    if (tid == 0) {
        float mm = sred[0];
        for (int i = 1; i < 8; i++) mm = fmaxf(mm, sred[i]);
        s_max = mm;
    }
    __syncthreads();
    float mx = s_max;

    float sum = 0.f;
    for (int r = tid; r < 1152; r += 256) sum += expf(g_bij[r * 10 + c] - mx);
    for (int off = 16; off >= 1; off >>= 1) sum += __shfl_xor_sync(~0u, sum, off);
    if (lane == 0) sred[warp] = sum;
    __syncthreads();
    if (tid == 0) {
        float ss = 0.f;
        for (int i = 0; i < 8; i++) ss += sred[i];
        s_sum = ss;
    }
    __syncthreads();
    float inv = 1.f / s_sum;
    for (int r = tid; r < 1152; r += 256)
        g_cij[r * 10 + c] = expf(g_bij[r * 10 + c] - mx) * inv;
}

// s[b,c,:] = sum_r c[r,c] * uhat[b][c][r][:]; v = sn*s/((1+sn)*sqrt(sn)) elementwise.
// grid (10, 256), 128 threads.
__global__ __launch_bounds__(128) void sv_kernel()
{
    int c = blockIdx.x, b = blockIdx.y;
    int tid = threadIdx.x;
    int lane = tid & 31, warp = tid >> 5;

    float acc[16];
    #pragma unroll
    for (int k = 0; k < 16; k++) acc[k] = 0.f;

    const float* ub = g_uhat + ((size_t)(b * 10 + c)) * 1152 * 16;
    for (int r = tid; r < 1152; r += 128) {
        float cw = g_cij[r * 10 + c];
        const float4* q = (const float4*)(ub + (size_t)r * 16);
        float4 q0 = q[0], q1 = q[1], q2 = q[2], q3 = q[3];
        acc[0]  = fmaf(cw, q0.x, acc[0]);  acc[1]  = fmaf(cw, q0.y, acc[1]);
        acc[2]  = fmaf(cw, q0.z, acc[2]);  acc[3]  = fmaf(cw, q0.w, acc[3]);
        acc[4]  = fmaf(cw, q1.x, acc[4]);  acc[5]  = fmaf(cw, q1.y, acc[5]);
        acc[6]  = fmaf(cw, q1.z, acc[6]);  acc[7]  = fmaf(cw, q1.w, acc[7]);
        acc[8]  = fmaf(cw, q2.x, acc[8]);  acc[9]  = fmaf(cw, q2.y, acc[9]);
        acc[10] = fmaf(cw, q2.z, acc[10]); acc[11] = fmaf(cw, q2.w, acc[11]);
        acc[12] = fmaf(cw, q3.x, acc[12]); acc[13] = fmaf(cw, q3.y, acc[13]);
        acc[14] = fmaf(cw, q3.z, acc[14]); acc[15] = fmaf(cw, q3.w, acc[15]);
    }
    #pragma unroll
    for (int k = 0; k < 16; k++)
        for (int off = 16; off >= 1; off >>= 1)
            acc[k] += __shfl_xor_sync(~0u, acc[k], off);

    __shared__ float sred[4][16];
    if (lane == 0)
        #pragma unroll
        for (int k = 0; k < 16; k++) sred[warp][k] = acc[k];
    __syncthreads();
    if (tid < 16) {
        float s = sred[0][tid] + sred[1][tid] + sred[2][tid] + sred[3][tid];
        float sn = s * s;
        float v = sn * s / ((1.f + sn) * sqrtf(sn));   // faithful elementwise quirk
        g_v[(b * 10 + c) * 16 + tid] = v;
    }
}

// b_ij[r,c] += (1/B) sum_b dot16(uhat[b][c][r][:], v[b][c][:]).  grid (1152,10), 256 thr.
__global__ __launch_bounds__(256) void agree_kernel()
{
    int r = blockIdx.x, c = blockIdx.y;
    int b = threadIdx.x;
    int lane = b & 31, warp = b >> 5;

    const float4* uq = (const float4*)(g_uhat + (((size_t)(b * 10 + c)) * 1152 + r) * 16);
    const float4* vq = (const float4*)(g_v + (b * 10 + c) * 16);
    float val = 0.f;
    #pragma unroll
    for (int q = 0; q < 4; q++) {
        float4 u4 = uq[q], v4 = vq[q];
        val += u4.x*v4.x + u4.y*v4.y + u4.z*v4.z + u4.w*v4.w;
    }
    for (int off = 16; off >= 1; off >>= 1) val += __shfl_xor_sync(~0u, val, off);
    __shared__ float sred[8];
    if (lane == 0) sred[warp] = val;
    __syncthreads();
    if (b == 0) {
        float s = 0.f;
        for (int i = 0; i < 8; i++) s += sred[i];
        g_bij[r * 10 + c] += s * (1.f / 256.f);
    }
}

// ---------------------------------------------------------------- mask / argmax
__global__ __launch_bounds__(256) void mask_kernel(float* __restrict__ out_masked)
{
    __shared__ float cls[256][10];
    __shared__ float colmax[10], colsum[10];
    int b = threadIdx.x;

    for (int c = 0; c < 10; c++) {
        const float* vp = g_v + (b * 10 + c) * 16;
        float sn = 0.f;
        #pragma unroll
        for (int o = 0; o < 16; o++) sn += vp[o] * vp[o];
        cls[b][c] = sqrtf(sn);
    }
    __syncthreads();
    if (b < 10) {
        float m = -1e30f;
        for (int i = 0; i < 256; i++) m = fmaxf(m, cls[i][b]);
        float s = 0.f;
        for (int i = 0; i < 256; i++) s += expf(cls[i][b] - m);
        colmax[b] = m; colsum[b] = s;
    }
    __syncthreads();
    float best = -1e30f; int bi = 0;
    for (int c = 0; c < 10; c++) {
        float val = expf(cls[b][c] - colmax[c]) / colsum[c];
        if (val > best) { best = val; bi = c; }   // first-occurrence argmax
    }
    g_idx[b] = bi;
    for (int c = 0; c < 10; c++) out_masked[b * 10 + c] = (c == bi) ? 1.f : 0.f;
}

// ---------------------------------------------------------------- decoder
__global__ __launch_bounds__(512) void fc1_kernel(
    const float* __restrict__ W1, const float* __restrict__ b1)
{
    int b = blockIdx.x;
    int j = threadIdx.x;
    int idx = g_idx[b];
    const float* vp = g_v + (b * 10 + idx) * 16;
    float acc = b1[j];
    #pragma unroll
    for (int o = 0; o < 16; o++)
        acc = fmaf(vp[o], W1[(idx * 16 + o) * 512 + j], acc);
    g_h1[b * 512 + j] = fmaxf(acc, 0.f);
}

// Generic tiled GEMM: C = act(A[M,K] * B[K,N] + bias). 64x64 tile, 256 thr, 4x4/thr.
__global__ __launch_bounds__(256) void gemm_kernel(
    const float* __restrict__ A, const float* __restrict__ Bm,
    const float* __restrict__ bias, float* __restrict__ C,
    int M, int N, int K, int act)
{
    __shared__ float As[16 * 65];
    __shared__ float Bs[16 * 64];
    int tid = threadIdx.x;
    int tx = tid & 15, ty = tid >> 4;
    int n0 = blockIdx.x * 64, m0 = blockIdx.y * 64;

    float cacc[4][4];
    #pragma unroll
    for (int i = 0; i < 4; i++)
        #pragma unroll
        for (int j = 0; j < 4; j++) cacc[i][j] = 0.f;

    for (int k0 = 0; k0 < K; k0 += 16) {
        for (int e = tid; e < 1024; e += 256) {
            int m = e >> 4, k = e & 15;
            float v = 0.f;
            if (m0 + m < M && k0 + k < K) v = A[(size_t)(m0 + m) * K + k0 + k];
            As[k * 65 + m] = v;
        }
        for (int e = tid; e < 1024; e += 256) {
            int k = e >> 6, n = e & 63;
            float v = 0.f;
            if (k0 + k < K && n0 + n < N) v = Bm[(size_t)(k0 + k) * N + n0 + n];
            Bs[k * 64 + n] = v;
        }
        __syncthreads();
        #pragma unroll
        for (int kk = 0; kk < 16; kk++) {
            float a0 = As[kk * 65 + ty * 4 + 0];
            float a1 = As[kk * 65 + ty * 4 + 1];
            float a2 = As[kk * 65 + ty * 4 + 2];
            float a3 = As[kk * 65 + ty * 4 + 3];
            float4 bv = *(float4*)(Bs + kk * 64 + tx * 4);
            cacc[0][0] = fmaf(a0, bv.x, cacc[0][0]); cacc[0][1] = fmaf(a0, bv.y, cacc[0][1]);
            cacc[0][2] = fmaf(a0, bv.z, cacc[0][2]); cacc[0][3] = fmaf(a0, bv.w, cacc[0][3]);
            cacc[1][0] = fmaf(a1, bv.x, cacc[1][0]); cacc[1][1] = fmaf(a1, bv.y, cacc[1][1]);
            cacc[1][2] = fmaf(a1, bv.z, cacc[1][2]); cacc[1][3] = fmaf(a1, bv.w, cacc[1][3]);
            cacc[2][0] = fmaf(a2, bv.x, cacc[2][0]); cacc[2][1] = fmaf(a2, bv.y, cacc[2][1]);
            cacc[2][2] = fmaf(a2, bv.z, cacc[2][2]); cacc[2][3] = fmaf(a2, bv.w, cacc[2][3]);
            cacc[3][0] = fmaf(a3, bv.x, cacc[3][0]); cacc[3][1] = fmaf(a3, bv.y, cacc[3][1]);
            cacc[3][2] = fmaf(a3, bv.z, cacc[3][2]); cacc[3][3] = fmaf(a3, bv.w, cacc[3][3]);
        }
        __syncthreads();
    }
    #pragma unroll
    for (int i = 0; i < 4; i++) {
        int m = m0 + ty * 4 + i;
        if (m >= M) continue;
        #pragma unroll
        for (int j = 0; j < 4; j++) {
            int n = n0 + tx * 4 + j;
            if (n >= N) continue;
            float v = cacc[i][j] + bias[n];
            if (act == 1) v = fmaxf(v, 0.f);
            else if (act == 2) v = 1.f / (1.f + expf(-v));
            C[(size_t)m * N + n] = v;
        }
    }
}

__global__ void copy_v_kernel(float* __restrict__ out_v)
{
    int i = blockIdx.x * blockDim.x + threadIdx.x;
    if (i < 40960) out_v[i] = g_v[i];
}

// ---------------------------------------------------------------- launch
extern "C" void kernel_launch(void* const* d_in, const int* in_sizes, int n_in,
                              void* d_out, int out_size)
{
    const float* x       = (const float*)d_in[0];
    const float* conv1_w = (const float*)d_in[1];
    const float* conv1_b = (const float*)d_in[2];
    const float* prim_w  = (const float*)d_in[3];
    const float* prim_b  = (const float*)d_in[4];
    const float* W_caps  = (const float*)d_in[5];
    const float* dec_w1  = (const float*)d_in[6];
    const float* dec_b1  = (const float*)d_in[7];
    const float* dec_w2  = (const float*)d_in[8];
    const float* dec_b2  = (const float*)d_in[9];
    const float* dec_w3  = (const float*)d_in[10];
    const float* dec_b3  = (const float*)d_in[11];
    float* out = (float*)d_out;

    const int OFF_V = 200704, OFF_REC = 241664, OFF_MASK = 442368;

    float *p_h1, *p_h2;
    cudaGetSymbolAddress((void**)&p_h1, g_h1);
    cudaGetSymbolAddress((void**)&p_h2, g_h2);

    cudaMemcpyAsync(out, x, 200704 * sizeof(float), cudaMemcpyDeviceToDevice);

    conv1_kernel<<<dim3(8, 256), 256>>>(x, conv1_w, conv1_b);
    prim_conv_kernel<<<dim3(2, 256), 192>>>(prim_w, prim_b);
    squash_kernel<<<(294912 + 255) / 256, 256>>>();
    uhat_kernel<<<1152, 160>>>(W_caps);
    zero_b_kernel<<<45, 256>>>();

    for (int it = 0; it < 3; it++) {
        softmax_kernel<<<10, 256>>>();
        sv_kernel<<<dim3(10, 256), 128>>>();
        if (it < 2) agree_kernel<<<dim3(1152, 10), 256>>>();
    }

    copy_v_kernel<<<40, 1024>>>(out + OFF_V);
    mask_kernel<<<1, 256>>>(out + OFF_MASK);

    fc1_kernel<<<256, 512>>>(dec_w1, dec_b1);
    gemm_kernel<<<dim3(16, 4), 256>>>(p_h1, dec_w2, dec_b2, p_h2, 256, 1024, 512, 1);
    gemm_kernel<<<dim3(13, 4), 256>>>(p_h2, dec_w3, dec_b3, out + OFF_REC, 256, 784, 1024, 2);
}

// round 5
// speedup vs baseline: 4.3711x; 4.3711x over previous
#include <cuda_runtime.h>
#include <cuda_bf16.h>
#include <math.h>
#include <stdint.h>

// ----------------------------------------------------------------------------
// CapsNet forward. PrimaryCaps conv runs on mma.sync bf16 (hi/lo 2-term
// emulation of fp32, fp32 accumulate in registers). tcgen05 is NOT available
// through this toolchain's compute_103 PTX target.
// Output layout (concatenated, float32):
//   [0, 200704)        x
//   [200704, 241664)   v (output) [B,10,16,1]
//   [241664, 442368)   reconstruction [B,1,28,28]
//   [442368, 444928)   masked one-hot [B,10]
// ----------------------------------------------------------------------------

__device__ __nv_bfloat16 g_yh[26214400]; // [256 b][400 pos][256 ic] NHWC hi
__device__ __nv_bfloat16 g_yl[26214400]; // lo
__device__ __nv_bfloat16 g_wh[5308416];  // [81 tap][256 oc][256 ic] hi
__device__ __nv_bfloat16 g_wl[5308416];  // lo
__device__ float g_u[2359296];           // [256][9216] primary caps (squashed in-place)
__device__ float g_uhat[47185920];       // [256][10][1152][16]
__device__ float g_bij[11520];
__device__ float g_cij[11520];
__device__ float g_v[40960];             // [256][10][16]
__device__ int   g_idx[256];
__device__ float g_h1[131072];
__device__ float g_h2[262144];

// ------------------------------------------------------------- ptx helpers
__device__ __forceinline__ uint32_t smem_u32(const void* p) {
    uint32_t a;
    asm("{ .reg .u64 t; cvta.to.shared.u64 t, %1; cvt.u32.u64 %0, t; }"
        : "=r"(a) : "l"(p));
    return a;
}

#define SWZ128(off) ((off) ^ (((off) >> 3) & 0x70))

__device__ __forceinline__ void cp16(uint32_t dst, const void* src) {
    asm volatile("cp.async.cg.shared.global [%0], [%1], 16;"
                 :: "r"(dst), "l"(src) : "memory");
}

__device__ __forceinline__ void ldsm4(uint32_t* r, uint32_t a) {
    asm volatile("ldmatrix.sync.aligned.m8n8.x4.shared.b16 {%0,%1,%2,%3}, [%4];"
                 : "=r"(r[0]), "=r"(r[1]), "=r"(r[2]), "=r"(r[3]) : "r"(a));
}

__device__ __forceinline__ void mma16816(float* d, const uint32_t* a, const uint32_t* bx) {
    asm volatile("mma.sync.aligned.m16n8k16.row.col.f32.bf16.bf16.f32 "
                 "{%0,%1,%2,%3}, {%4,%5,%6,%7}, {%8,%9}, {%0,%1,%2,%3};"
                 : "+f"(d[0]), "+f"(d[1]), "+f"(d[2]), "+f"(d[3])
                 : "r"(a[0]), "r"(a[1]), "r"(a[2]), "r"(a[3]),
                   "r"(bx[0]), "r"(bx[1]));
}

// ---------------------------------------------------------------- conv1
// grid (8 ocTiles, 256 batch), 256 threads. Writes NHWC bf16 hi/lo.
__global__ __launch_bounds__(256) void conv1_kernel(
    const float* __restrict__ x, const float* __restrict__ w,
    const float* __restrict__ bias)
{
    int oct = blockIdx.x;
    int b   = blockIdx.y;
    int tid = threadIdx.x;

    __shared__ float simg[784];
    __shared__ float sw[32 * 81];

    for (int e = tid; e < 784; e += 256)  simg[e] = x[b * 784 + e];
    for (int e = tid; e < 2592; e += 256) sw[e]   = w[oct * 2592 + e];
    __syncthreads();

    int posA = tid;
    int posB = tid + 256;
    bool hasB = (posB < 400);
    int oyA = posA / 20, oxA = posA % 20;
    int oyB = posB / 20, oxB = posB % 20;
    if (!hasB) { oyB = 0; oxB = 0; }

    for (int ocg = 0; ocg < 4; ocg++) {
        float accA[8], accB[8];
        #pragma unroll
        for (int j = 0; j < 8; j++) { accA[j] = 0.f; accB[j] = 0.f; }

        for (int ky = 0; ky < 9; ky++) {
            #pragma unroll
            for (int kx = 0; kx < 9; kx++) {
                float iA = simg[(oyA + ky) * 28 + oxA + kx];
                float iB = simg[(oyB + ky) * 28 + oxB + kx];
                const float* wp = sw + (ocg * 8) * 81 + ky * 9 + kx;
                #pragma unroll
                for (int j = 0; j < 8; j++) {
                    float wv = wp[j * 81];
                    accA[j] = fmaf(wv, iA, accA[j]);
                    accB[j] = fmaf(wv, iB, accB[j]);
                }
            }
        }
        int ocb = oct * 32 + ocg * 8;
        __align__(16) __nv_bfloat16 hA[8], lA[8], hB[8], lB[8];
        #pragma unroll
        for (int j = 0; j < 8; j++) {
            float bb = bias[ocb + j];
            float vA = fmaxf(accA[j] + bb, 0.f);
            hA[j] = __float2bfloat16(vA);
            lA[j] = __float2bfloat16(vA - __bfloat162float(hA[j]));
            float vB = fmaxf(accB[j] + bb, 0.f);
            hB[j] = __float2bfloat16(vB);
            lB[j] = __float2bfloat16(vB - __bfloat162float(hB[j]));
        }
        size_t baseA = ((size_t)b * 400 + posA) * 256 + ocb;
        *(uint4*)(g_yh + baseA) = *(const uint4*)hA;
        *(uint4*)(g_yl + baseA) = *(const uint4*)lA;
        if (hasB) {
            size_t baseB = ((size_t)b * 400 + posB) * 256 + ocb;
            *(uint4*)(g_yh + baseB) = *(const uint4*)hB;
            *(uint4*)(g_yl + baseB) = *(const uint4*)lB;
        }
    }
}

// ---------------------------------------------------------------- weight prep
// prim_w OIHW [256 oc][256 ic][9][9] -> wt[t][oc][ic] bf16 hi/lo
__global__ void wprep_kernel(const float* __restrict__ w)
{
    int i = blockIdx.x * blockDim.x + threadIdx.x;
    if (i >= 5308416) return;
    int ic = i & 255;
    int rest = i >> 8;
    int oc = rest & 255;
    int t = rest >> 8;
    float v = w[((size_t)oc * 256 + ic) * 81 + t];
    __nv_bfloat16 h = __float2bfloat16(v);
    g_wh[i] = h;
    g_wl[i] = __float2bfloat16(v - __bfloat162float(h));
}

// ---------------------------------------------------------------- primary conv (mma.sync)
// grid (72 m-tiles, 2 oc-halves), 256 threads = 8 warps (4 m-quarters x 2 n-halves).
// M=128 rows (b,pos), N=128 oc. 324 stages of K=64 (81 taps x 4 ic-chunks).
// Per k16-step: 3 mma terms (hi*hi, hi*lo, lo*hi). cp.async double-buffered.
#define BUF_SZ 65536
#define OFF_AH 0
#define OFF_AL 16384
#define OFF_BH 32768
#define OFF_BL 49152
#define PRIM_SMEM (1024 + 2 * BUF_SZ)

__global__ __launch_bounds__(256) void prim_mma_kernel(const float* __restrict__ pb)
{
    extern __shared__ char smem[];
    uint32_t sb = smem_u32(smem) + 1024;
    int tid  = threadIdx.x;
    int lane = tid & 31, wid = tid >> 5;
    int mtile = blockIdx.x;
    int half  = blockIdx.y;
    int wm = wid & 3;      // m quarter (32 rows)
    int wn = wid >> 2;     // n half (64 cols)

    // loader mapping: 2 threads per row, 4 x 16B chunks each
    int rl  = tid >> 1;
    int sub = tid & 1;
    int rg  = mtile * 128 + rl;
    int b   = rg / 36;
    int pos = rg - b * 36;
    int oy  = pos / 6;
    int ox  = pos - oy * 6;
    int iy0 = 2 * oy, ix0 = 2 * ox;

    uint32_t sts[4];
    #pragma unroll
    for (int i = 0; i < 4; i++) {
        uint32_t o = rl * 128 + sub * 64 + i * 16;
        sts[i] = SWZ128(o);
    }

    #define LOAD_STAGE(s, bufb) do {                                           \
        int t_   = (s) >> 2;                                                   \
        int ic0_ = ((s) & 3) << 6;                                             \
        int ky_  = t_ / 9;                                                     \
        int kx_  = t_ - ky_ * 9;                                               \
        uint32_t aoff = (uint32_t)((b * 20 + iy0 + ky_) * 20 + ix0 + kx_) * 256 \
                        + ic0_ + sub * 32;                                     \
        uint32_t boff = (uint32_t)t_ * 65536                                   \
                        + (uint32_t)(half * 128 + rl) * 256 + ic0_ + sub * 32; \
        _Pragma("unroll")                                                      \
        for (int i_ = 0; i_ < 4; i_++) {                                       \
            cp16((bufb) + OFF_AH + sts[i_], g_yh + aoff + i_ * 8);             \
            cp16((bufb) + OFF_AL + sts[i_], g_yl + aoff + i_ * 8);             \
            cp16((bufb) + OFF_BH + sts[i_], g_wh + boff + i_ * 8);             \
            cp16((bufb) + OFF_BL + sts[i_], g_wl + boff + i_ * 8);             \
        }                                                                      \
        asm volatile("cp.async.commit_group;" ::: "memory");                   \
    } while (0)

    float acc[2][8][4];
    #pragma unroll
    for (int f = 0; f < 2; f++)
        #pragma unroll
        for (int j = 0; j < 8; j++)
            #pragma unroll
            for (int q = 0; q < 4; q++) acc[f][j][q] = 0.f;

    LOAD_STAGE(0, sb);

    // precompute ldmatrix lane-offset components (k-independent parts)
    uint32_t a_row = (uint32_t)(wm * 32 + (lane & 15)) * 128 + ((lane >> 4) << 4);
    uint32_t b_row = (uint32_t)(wn * 64 + ((lane & 7) | (((lane >> 4) & 1) << 3))) * 128
                     + (((lane >> 3) & 1) << 4);

    const int NSTAGE = 324;
    for (int s = 0; s < NSTAGE; s++) {
        uint32_t cur = sb + (uint32_t)(s & 1) * BUF_SZ;
        if (s + 1 < NSTAGE) {
            uint32_t nxt = sb + (uint32_t)((s + 1) & 1) * BUF_SZ;
            LOAD_STAGE(s + 1, nxt);
            asm volatile("cp.async.wait_group 1;" ::: "memory");
        } else {
            asm volatile("cp.async.wait_group 0;" ::: "memory");
        }
        __syncthreads();

        #pragma unroll
        for (int ks = 0; ks < 4; ks++) {
            uint32_t Ah[2][4], Al[2][4];
            #pragma unroll
            for (int f = 0; f < 2; f++) {
                uint32_t sw = SWZ128(a_row + (uint32_t)f * 16 * 128 + ks * 32);
                ldsm4(Ah[f], cur + OFF_AH + sw);
                ldsm4(Al[f], cur + OFF_AL + sw);
            }
            uint32_t Bh[4][4], Bl[4][4];
            #pragma unroll
            for (int g = 0; g < 4; g++) {
                uint32_t sw = SWZ128(b_row + (uint32_t)g * 16 * 128 + ks * 32);
                ldsm4(Bh[g], cur + OFF_BH + sw);
                ldsm4(Bl[g], cur + OFF_BL + sw);
            }
            #pragma unroll
            for (int f = 0; f < 2; f++)
                #pragma unroll
                for (int g = 0; g < 4; g++)
                    #pragma unroll
                    for (int h = 0; h < 2; h++) {
                        int j = g * 2 + h;
                        mma16816(acc[f][j], Ah[f], &Bh[g][h * 2]);
                        mma16816(acc[f][j], Ah[f], &Bl[g][h * 2]);
                        mma16816(acc[f][j], Al[f], &Bh[g][h * 2]);
                    }
        }
        __syncthreads();
    }

    // epilogue: acc[f][j][q] -> D[m][n], m = mtile*128 + wm*32 + f*16 + lane/4 (+8),
    // n = half*128 + wn*64 + j*8 + (lane%4)*2 (+1)
    int mb = mtile * 128 + wm * 32 + (lane >> 2);
    int nb = half * 128 + wn * 64 + (lane & 3) * 2;
    #pragma unroll
    for (int f = 0; f < 2; f++) {
        int m0 = mb + f * 16;
        int b0 = m0 / 36,      p0 = m0 - b0 * 36;
        int m1 = m0 + 8;
        int b1 = m1 / 36,      p1 = m1 - b1 * 36;
        float* u0 = g_u + (size_t)b0 * 9216 + p0;
        float* u1 = g_u + (size_t)b1 * 9216 + p1;
        #pragma unroll
        for (int j = 0; j < 8; j++) {
            int n = nb + j * 8;
            float bi0 = pb[n], bi1 = pb[n + 1];
            u0[(size_t)n * 36]       = acc[f][j][0] + bi0;
            u0[(size_t)(n + 1) * 36] = acc[f][j][1] + bi1;
            u1[(size_t)n * 36]       = acc[f][j][2] + bi0;
            u1[(size_t)(n + 1) * 36] = acc[f][j][3] + bi1;
        }
    }
}

// ---------------------------------------------------------------- squash (groups of 8)
__global__ void squash_kernel()
{
    int idx = blockIdx.x * blockDim.x + threadIdx.x;
    if (idx >= 294912) return;
    float* p = g_u + (size_t)idx * 8;
    float4 a = *(float4*)p;
    float4 c = *(float4*)(p + 4);
    float sn = a.x*a.x + a.y*a.y + a.z*a.z + a.w*a.w
             + c.x*c.x + c.y*c.y + c.z*c.z + c.w*c.w;
    float f = sn / ((1.f + sn) * sqrtf(sn));
    a.x*=f; a.y*=f; a.z*=f; a.w*=f; c.x*=f; c.y*=f; c.z*=f; c.w*=f;
    *(float4*)p = a;
    *(float4*)(p + 4) = c;
}

// ---------------------------------------------------------------- u_hat
__global__ __launch_bounds__(160) void uhat_kernel(const float* __restrict__ W)
{
    int r   = blockIdx.x;
    int tid = threadIdx.x;
    int c = tid >> 4, o = tid & 15;

    const float* wp = W + (((size_t)r * 10 + c) * 16 + o) * 8;
    float4 wa = *(const float4*)wp;
    float4 wb = *(const float4*)(wp + 4);

    __shared__ float su[32][8];

    for (int b0 = 0; b0 < 256; b0 += 32) {
        for (int e = tid; e < 256; e += 160) {
            int j = e >> 3, i = e & 7;
            su[j][i] = g_u[(size_t)(b0 + j) * 9216 + r * 8 + i];
        }
        __syncthreads();
        #pragma unroll 4
        for (int j = 0; j < 32; j++) {
            const float* uu = su[j];
            float s = wa.x*uu[0] + wa.y*uu[1] + wa.z*uu[2] + wa.w*uu[3]
                    + wb.x*uu[4] + wb.y*uu[5] + wb.z*uu[6] + wb.w*uu[7];
            g_uhat[(((size_t)(b0 + j) * 10 + c) * 1152 + r) * 16 + o] = s;
        }
        __syncthreads();
    }
}

// ---------------------------------------------------------------- routing
__global__ void zero_b_kernel()
{
    int i = blockIdx.x * blockDim.x + threadIdx.x;
    if (i < 11520) g_bij[i] = 0.f;
}

__global__ void softmax_kernel()
{
    int c   = blockIdx.x;
    int tid = threadIdx.x;
    int lane = tid & 31, warp = tid >> 5;
    __shared__ float sred[8];
    __shared__ float s_max, s_sum;

    float m = -1e30f;
    for (int r = tid; r < 1152; r += 256) m = fmaxf(m, g_bij[r * 10 + c]);
    for (int off = 16; off >= 1; off >>= 1) m = fmaxf(m, __shfl_xor_sync(~0u, m, off));
    if (lane == 0) sred[warp] = m;
    __syncthreads();
    if (tid == 0) {
        float mm = sred[0];
        for (int i = 1; i < 8; i++) mm = fmaxf(mm, sred[i]);
        s_max = mm;
    }
    __syncthreads();
    float mx = s_max;

    float sum = 0.f;
    for (int r = tid; r < 1152; r += 256) sum += expf(g_bij[r * 10 + c] - mx);
    for (int off = 16; off >= 1; off >>= 1) sum += __shfl_xor_sync(~0u, sum, off);
    if (lane == 0) sred[warp] = sum;
    __syncthreads();
    if (tid == 0) {
        float ss = 0.f;
        for (int i = 0; i < 8; i++) ss += sred[i];
        s_sum = ss;
    }
    __syncthreads();
    float inv = 1.f / s_sum;
    for (int r = tid; r < 1152; r += 256)
        g_cij[r * 10 + c] = expf(g_bij[r * 10 + c] - mx) * inv;
}

__global__ __launch_bounds__(128) void sv_kernel()
{
    int c = blockIdx.x, b = blockIdx.y;
    int tid = threadIdx.x;
    int lane = tid & 31, warp = tid >> 5;

    float acc[16];
    #pragma unroll
    for (int k = 0; k < 16; k++) acc[k] = 0.f;

    const float* ub = g_uhat + ((size_t)(b * 10 + c)) * 1152 * 16;
    for (int r = tid; r < 1152; r += 128) {
        float cw = g_cij[r * 10 + c];
        const float4* q = (const float4*)(ub + (size_t)r * 16);
        float4 q0 = q[0], q1 = q[1], q2 = q[2], q3 = q[3];
        acc[0]  = fmaf(cw, q0.x, acc[0]);  acc[1]  = fmaf(cw, q0.y, acc[1]);
        acc[2]  = fmaf(cw, q0.z, acc[2]);  acc[3]  = fmaf(cw, q0.w, acc[3]);
        acc[4]  = fmaf(cw, q1.x, acc[4]);  acc[5]  = fmaf(cw, q1.y, acc[5]);
        acc[6]  = fmaf(cw, q1.z, acc[6]);  acc[7]  = fmaf(cw, q1.w, acc[7]);
        acc[8]  = fmaf(cw, q2.x, acc[8]);  acc[9]  = fmaf(cw, q2.y, acc[9]);
        acc[10] = fmaf(cw, q2.z, acc[10]); acc[11] = fmaf(cw, q2.w, acc[11]);
        acc[12] = fmaf(cw, q3.x, acc[12]); acc[13] = fmaf(cw, q3.y, acc[13]);
        acc[14] = fmaf(cw, q3.z, acc[14]); acc[15] = fmaf(cw, q3.w, acc[15]);
    }
    #pragma unroll
    for (int k = 0; k < 16; k++)
        for (int off = 16; off >= 1; off >>= 1)
            acc[k] += __shfl_xor_sync(~0u, acc[k], off);

    __shared__ float sred[4][16];
    if (lane == 0)
        #pragma unroll
        for (int k = 0; k < 16; k++) sred[warp][k] = acc[k];
    __syncthreads();
    if (tid < 16) {
        float s = sred[0][tid] + sred[1][tid] + sred[2][tid] + sred[3][tid];
        float sn = s * s;
        float v = sn * s / ((1.f + sn) * sqrtf(sn));
        g_v[(b * 10 + c) * 16 + tid] = v;
    }
}

__global__ __launch_bounds__(256) void agree_kernel()
{
    int r = blockIdx.x, c = blockIdx.y;
    int b = threadIdx.x;
    int lane = b & 31, warp = b >> 5;

    const float4* uq = (const float4*)(g_uhat + (((size_t)(b * 10 + c)) * 1152 + r) * 16);
    const float4* vq = (const float4*)(g_v + (b * 10 + c) * 16);
    float val = 0.f;
    #pragma unroll
    for (int q = 0; q < 4; q++) {
        float4 u4 = uq[q], v4 = vq[q];
        val += u4.x*v4.x + u4.y*v4.y + u4.z*v4.z + u4.w*v4.w;
    }
    for (int off = 16; off >= 1; off >>= 1) val += __shfl_xor_sync(~0u, val, off);
    __shared__ float sred[8];
    if (lane == 0) sred[warp] = val;
    __syncthreads();
    if (b == 0) {
        float s = 0.f;
        for (int i = 0; i < 8; i++) s += sred[i];
        g_bij[r * 10 + c] += s * (1.f / 256.f);
    }
}

// ---------------------------------------------------------------- mask / argmax
__global__ __launch_bounds__(256) void mask_kernel(float* __restrict__ out_masked)
{
    __shared__ float cls[256][10];
    __shared__ float colmax[10], colsum[10];
    int b = threadIdx.x;

    for (int c = 0; c < 10; c++) {
        const float* vp = g_v + (b * 10 + c) * 16;
        float sn = 0.f;
        #pragma unroll
        for (int o = 0; o < 16; o++) sn += vp[o] * vp[o];
        cls[b][c] = sqrtf(sn);
    }
    __syncthreads();
    if (b < 10) {
        float m = -1e30f;
        for (int i = 0; i < 256; i++) m = fmaxf(m, cls[i][b]);
        float s = 0.f;
        for (int i = 0; i < 256; i++) s += expf(cls[i][b] - m);
        colmax[b] = m; colsum[b] = s;
    }
    __syncthreads();
    float best = -1e30f; int bi = 0;
    for (int c = 0; c < 10; c++) {
        float val = expf(cls[b][c] - colmax[c]) / colsum[c];
        if (val > best) { best = val; bi = c; }
    }
    g_idx[b] = bi;
    for (int c = 0; c < 10; c++) out_masked[b * 10 + c] = (c == bi) ? 1.f : 0.f;
}

// ---------------------------------------------------------------- decoder
__global__ __launch_bounds__(512) void fc1_kernel(
    const float* __restrict__ W1, const float* __restrict__ b1)
{
    int b = blockIdx.x;
    int j = threadIdx.x;
    int idx = g_idx[b];
    const float* vp = g_v + (b * 10 + idx) * 16;
    float acc = b1[j];
    #pragma unroll
    for (int o = 0; o < 16; o++)
        acc = fmaf(vp[o], W1[(idx * 16 + o) * 512 + j], acc);
    g_h1[b * 512 + j] = fmaxf(acc, 0.f);
}

__global__ __launch_bounds__(256) void gemm_kernel(
    const float* __restrict__ A, const float* __restrict__ Bm,
    const float* __restrict__ bias, float* __restrict__ C,
    int M, int N, int K, int act)
{
    __shared__ float As[16 * 65];
    __shared__ float Bs[16 * 64];
    int tid = threadIdx.x;
    int tx = tid & 15, ty = tid >> 4;
    int n0 = blockIdx.x * 64, m0 = blockIdx.y * 64;

    float cacc[4][4];
    #pragma unroll
    for (int i = 0; i < 4; i++)
        #pragma unroll
        for (int j = 0; j < 4; j++) cacc[i][j] = 0.f;

    for (int k0 = 0; k0 < K; k0 += 16) {
        for (int e = tid; e < 1024; e += 256) {
            int m = e >> 4, k = e & 15;
            float v = 0.f;
            if (m0 + m < M && k0 + k < K) v = A[(size_t)(m0 + m) * K + k0 + k];
            As[k * 65 + m] = v;
        }
        for (int e = tid; e < 1024; e += 256) {
            int k = e >> 6, n = e & 63;
            float v = 0.f;
            if (k0 + k < K && n0 + n < N) v = Bm[(size_t)(k0 + k) * N + n0 + n];
            Bs[k * 64 + n] = v;
        }
        __syncthreads();
        #pragma unroll
        for (int kk = 0; kk < 16; kk++) {
            float a0 = As[kk * 65 + ty * 4 + 0];
            float a1 = As[kk * 65 + ty * 4 + 1];
            float a2 = As[kk * 65 + ty * 4 + 2];
            float a3 = As[kk * 65 + ty * 4 + 3];
            float4 bv = *(float4*)(Bs + kk * 64 + tx * 4);
            cacc[0][0] = fmaf(a0, bv.x, cacc[0][0]); cacc[0][1] = fmaf(a0, bv.y, cacc[0][1]);
            cacc[0][2] = fmaf(a0, bv.z, cacc[0][2]); cacc[0][3] = fmaf(a0, bv.w, cacc[0][3]);
            cacc[1][0] = fmaf(a1, bv.x, cacc[1][0]); cacc[1][1] = fmaf(a1, bv.y, cacc[1][1]);
            cacc[1][2] = fmaf(a1, bv.z, cacc[1][2]); cacc[1][3] = fmaf(a1, bv.w, cacc[1][3]);
            cacc[2][0] = fmaf(a2, bv.x, cacc[2][0]); cacc[2][1] = fmaf(a2, bv.y, cacc[2][1]);
            cacc[2][2] = fmaf(a2, bv.z, cacc[2][2]); cacc[2][3] = fmaf(a2, bv.w, cacc[2][3]);
            cacc[3][0] = fmaf(a3, bv.x, cacc[3][0]); cacc[3][1] = fmaf(a3, bv.y, cacc[3][1]);
            cacc[3][2] = fmaf(a3, bv.z, cacc[3][2]); cacc[3][3] = fmaf(a3, bv.w, cacc[3][3]);
        }
        __syncthreads();
    }
    #pragma unroll
    for (int i = 0; i < 4; i++) {
        int m = m0 + ty * 4 + i;
        if (m >= M) continue;
        #pragma unroll
        for (int j = 0; j < 4; j++) {
            int n = n0 + tx * 4 + j;
            if (n >= N) continue;
            float v = cacc[i][j] + bias[n];
            if (act == 1) v = fmaxf(v, 0.f);
            else if (act == 2) v = 1.f / (1.f + expf(-v));
            C[(size_t)m * N + n] = v;
        }
    }
}

__global__ void copy_v_kernel(float* __restrict__ out_v)
{
    int i = blockIdx.x * blockDim.x + threadIdx.x;
    if (i < 40960) out_v[i] = g_v[i];
}

// ---------------------------------------------------------------- launch
extern "C" void kernel_launch(void* const* d_in, const int* in_sizes, int n_in,
                              void* d_out, int out_size)
{
    const float* x       = (const float*)d_in[0];
    const float* conv1_w = (const float*)d_in[1];
    const float* conv1_b = (const float*)d_in[2];
    const float* prim_w  = (const float*)d_in[3];
    const float* prim_b  = (const float*)d_in[4];
    const float* W_caps  = (const float*)d_in[5];
    const float* dec_w1  = (const float*)d_in[6];
    const float* dec_b1  = (const float*)d_in[7];
    const float* dec_w2  = (const float*)d_in[8];
    const float* dec_b2  = (const float*)d_in[9];
    const float* dec_w3  = (const float*)d_in[10];
    const float* dec_b3  = (const float*)d_in[11];
    float* out = (float*)d_out;

    const int OFF_V = 200704, OFF_REC = 241664, OFF_MASK = 442368;

    float *p_h1, *p_h2;
    cudaGetSymbolAddress((void**)&p_h1, g_h1);
    cudaGetSymbolAddress((void**)&p_h2, g_h2);

    cudaFuncSetAttribute(prim_mma_kernel,
                         cudaFuncAttributeMaxDynamicSharedMemorySize, PRIM_SMEM);

    cudaMemcpyAsync(out, x, 200704 * sizeof(float), cudaMemcpyDeviceToDevice);

    wprep_kernel<<<(5308416 + 255) / 256, 256>>>(prim_w);
    conv1_kernel<<<dim3(8, 256), 256>>>(x, conv1_w, conv1_b);
    prim_mma_kernel<<<dim3(72, 2), 256, PRIM_SMEM>>>(prim_b);
    squash_kernel<<<(294912 + 255) / 256, 256>>>();
    uhat_kernel<<<1152, 160>>>(W_caps);
    zero_b_kernel<<<45, 256>>>();

    for (int it = 0; it < 3; it++) {
        softmax_kernel<<<10, 256>>>();
        sv_kernel<<<dim3(10, 256), 128>>>();
        if (it < 2) agree_kernel<<<dim3(1152, 10), 256>>>();
    }

    copy_v_kernel<<<40, 1024>>>(out + OFF_V);
    mask_kernel<<<1, 256>>>(out + OFF_MASK);

    fc1_kernel<<<256, 512>>>(dec_w1, dec_b1);
    gemm_kernel<<<dim3(16, 4), 256>>>(p_h1, dec_w2, dec_b2, p_h2, 256, 1024, 512, 1);
    gemm_kernel<<<dim3(13, 4), 256>>>(p_h2, dec_w3, dec_b3, out + OFF_REC, 256, 784, 1024, 2);
}